// round 13
// baseline (speedup 1.0000x reference)
#include <cuda_runtime.h>
#include <cuda_fp16.h>
#include <math.h>
#include <cstdint>

#define BATCH 4096
#define TSTEPS 60
#define FDIM 128
#define HDIM 256
#define FH 384

// ---------------- device scratch (allocation-free rule) ----------------
__device__ __half g_xh[(size_t)BATCH * TSTEPS * FDIM];
__device__ __half g_hh[2][(size_t)BATCH * HDIM];
__device__ float  g_c[(size_t)BATCH * HDIM];
__device__ __half g_Wh[(size_t)1024 * FH];   // [gate*256+col][k] fp16 weights
__device__ __half g_pre[(size_t)TSTEPS * 32 * 4 * 32768];  // precomputed x-part preacts (+bias), fp16 fragment layout
__device__ float  g_weff[HDIM];
__device__ float  g_beff;

__device__ __forceinline__ float sigmoidf_(float x) { return 1.0f / (1.0f + __expf(-x)); }

__device__ __forceinline__ uint32_t smem_u32(const void* p) {
    uint32_t a;
    asm("{ .reg .u64 t; cvta.to.shared.u64 t, %1; cvt.u32.u64 %0, t; }" : "=r"(a) : "l"(p));
    return a;
}

#define LD4(R, ADDR) \
    asm volatile("ldmatrix.sync.aligned.m8n8.x4.shared.b16 {%0,%1,%2,%3}, [%4];" \
        : "=r"((R)[0]), "=r"((R)[1]), "=r"((R)[2]), "=r"((R)[3]) : "r"(ADDR))

#define MMA16816(C, A, B0, B1) \
    asm volatile("mma.sync.aligned.m16n8k16.row.col.f32.f16.f16.f32 " \
        "{%0,%1,%2,%3}, {%4,%5,%6,%7}, {%8,%9}, {%0,%1,%2,%3};" \
        : "+f"((C)[0]), "+f"((C)[1]), "+f"((C)[2]), "+f"((C)[3]) \
        : "r"((A)[0]), "r"((A)[1]), "r"((A)[2]), "r"((A)[3]), "r"(B0), "r"(B1))

#define CP16(SADDR, GADDR) \
    asm volatile("cp.async.cg.shared.global [%0], [%1], 16;" :: "r"(SADDR), "l"(GADDR))
#define CP_COMMIT() asm volatile("cp.async.commit_group;")
#define CP_WAITG(N) asm volatile("cp.async.wait_group %0;" :: "n"(N))

// ---------------- prep kernels ----------------
__global__ void split_x_kernel(const float* __restrict__ x) {
    size_t i = (size_t)blockIdx.x * blockDim.x + threadIdx.x;
    if (i < (size_t)BATCH * TSTEPS * FDIM) g_xh[i] = __float2half(x[i]);
}

__global__ void build_WT_kernel(const float* __restrict__ Wf, const float* __restrict__ Wu,
                                const float* __restrict__ Wc, const float* __restrict__ Wo) {
    int gr = blockIdx.x;                 // 0..1023
    int g = gr >> 8, col = gr & 255;
    const float* W = (g == 0) ? Wf : (g == 1) ? Wu : (g == 2) ? Wc : Wo;
    for (int k = threadIdx.x; k < FH; k += blockDim.x) {
        g_Wh[(size_t)gr * FH + k] = __float2half(W[(size_t)k * HDIM + col]);
    }
}

__global__ void weff_kernel(const float* __restrict__ Wd1, const float* __restrict__ bd1,
                            const float* __restrict__ Wd2, const float* __restrict__ bd2) {
    int w = (blockIdx.x * blockDim.x + threadIdx.x) >> 5;
    int lane = threadIdx.x & 31;
    if (w < HDIM) {
        float s = 0.0f;
        #pragma unroll
        for (int k = lane; k < HDIM; k += 32) s += Wd1[(size_t)w * HDIM + k] * Wd2[k];
        #pragma unroll
        for (int off = 16; off > 0; off >>= 1) s += __shfl_down_sync(0xffffffffu, s, off);
        if (lane == 0) g_weff[w] = s;
    }
    if (blockIdx.x == 0 && threadIdx.x < 32) {
        float b = 0.0f;
        #pragma unroll
        for (int k = lane; k < HDIM; k += 32) b += bd1[k] * Wd2[k];
        #pragma unroll
        for (int off = 16; off > 0; off >>= 1) b += __shfl_down_sync(0xffffffffu, b, off);
        if (lane == 0) g_beff = b + bd2[0];
    }
}

// ---------------- shared tile constants (A + B only, single fp16 pass) ----------------
#define A_OFF 0
#define B_OFF 10240
#define STAGE_SZ 30720
#define NSTAGE 3
#define SMEM_TOTAL (NSTAGE * STAGE_SZ)   // 90 KB

// ---------------- precompute x-part preacts for all steps (parallel GEMM) ----------------
__global__ __launch_bounds__(512, 1)
void xpre_kernel(const float* __restrict__ bfv, const float* __restrict__ buv,
                 const float* __restrict__ bcv, const float* __restrict__ bov) {
    extern __shared__ __align__(128) char smem[];
    const uint32_t sbase = smem_u32(smem);
    const int tid = threadIdx.x;
    const int warp = tid >> 5;
    const int lane = tid & 31;
    const int wm = warp >> 2;
    const int wn = warp & 3;
    const int px = blockIdx.x;       // (t, mg)
    const int t = px >> 5;
    const int mg = px & 31;
    const int m0 = mg * 128;
    const int ny = blockIdx.y;

    const int grp = lane >> 3, lr = lane & 7;

    float acc[4][2][2][4];
    #pragma unroll
    for (int g = 0; g < 4; ++g)
        #pragma unroll
        for (int i = 0; i < 2; ++i)
            #pragma unroll
            for (int s = 0; s < 2; ++s)
                #pragma unroll
                for (int q = 0; q < 4; ++q) acc[g][i][s][q] = 0.0f;

    auto issue_chunk = [&](int c) {
        uint32_t bb = sbase + (uint32_t)((c % NSTAGE) * STAGE_SZ);
        {
            int row = tid >> 2, seg = tid & 3;
            size_t s = ((size_t)(m0 + row) * TSTEPS + t) * FDIM + c * 32 + seg * 8;
            CP16(bb + A_OFF + (uint32_t)(row * 80 + seg * 16), &g_xh[s]);
        }
        #pragma unroll
        for (int e = 0; e < 2; ++e) {
            int idx = tid + e * 512;
            int row = idx >> 2, seg = idx & 3;
            int gr = ((row >> 6) << 8) + ny * 64 + (row & 63);
            size_t s = (size_t)gr * FH + c * 32 + seg * 8;
            CP16(bb + B_OFF + (uint32_t)(row * 80 + seg * 16), &g_Wh[s]);
        }
        CP_COMMIT();
    };

    issue_chunk(0);
    issue_chunk(1);

    for (int c = 0; c < 4; ++c) {
        if (c < 3) { CP_WAITG(1); } else { CP_WAITG(0); }
        __syncthreads();
        if (c + 2 < 4) issue_chunk(c + 2);

        const uint32_t bufb = sbase + (uint32_t)((c % NSTAGE) * STAGE_SZ);
        #pragma unroll
        for (int kh = 0; kh < 2; ++kh) {
            uint32_t ah[2][4];
            const int acol = kh * 32 + (grp >> 1) * 16;
            #pragma unroll
            for (int i = 0; i < 2; ++i) {
                int arow = wm * 32 + i * 16 + (grp & 1) * 8 + lr;
                LD4(ah[i], bufb + A_OFF + (uint32_t)(arow * 80 + acol));
            }
            const int bcol = kh * 32 + (grp & 1) * 16;
            #pragma unroll
            for (int g = 0; g < 4; ++g) {
                uint32_t bh[4];
                int brow = g * 64 + wn * 16 + ((grp >> 1) << 3) + lr;
                LD4(bh, bufb + B_OFF + (uint32_t)(brow * 80 + bcol));
                #pragma unroll
                for (int i = 0; i < 2; ++i)
                    #pragma unroll
                    for (int s2 = 0; s2 < 2; ++s2) {
                        MMA16816(acc[g][i][s2], ah[i], bh[s2 * 2], bh[s2 * 2 + 1]);
                    }
            }
        }
    }

    // fold biases, store fragments as fp16
    size_t blk = (((size_t)t * 32 + mg) * 4 + ny) * 32768;
    #pragma unroll
    for (int g = 0; g < 4; ++g) {
        const float* bp = (g == 0) ? bfv : (g == 1) ? buv : (g == 2) ? bcv : bov;
        #pragma unroll
        for (int i = 0; i < 2; ++i)
            #pragma unroll
            for (int s2 = 0; s2 < 2; ++s2) {
                const int col = ny * 64 + wn * 16 + s2 * 8 + (lane & 3) * 2;
                float2 b2 = *(const float2*)&bp[col];
                __half2 h01 = __halves2half2(__float2half(acc[g][i][s2][0] + b2.x),
                                             __float2half(acc[g][i][s2][1] + b2.y));
                __half2 h23 = __halves2half2(__float2half(acc[g][i][s2][2] + b2.x),
                                             __float2half(acc[g][i][s2][3] + b2.y));
                int fq = (g * 2 + i) * 2 + s2;
                uint2 v;
                v.x = *(uint32_t*)&h01;
                v.y = *(uint32_t*)&h23;
                *(uint2*)&g_pre[blk + (size_t)fq * 2048 + tid * 4] = v;
            }
    }
}

// ---------------- step kernel (h-part only, 8 chunks, single fp16 pass) ----------------
__global__ __launch_bounds__(512, 1)
void lstm_step_mma(int t) {
    extern __shared__ __align__(128) char smem[];
    const uint32_t sbase = smem_u32(smem);
    const int tid = threadIdx.x;
    const int warp = tid >> 5;
    const int lane = tid & 31;
    const int wm = warp >> 2;
    const int wn = warp & 3;
    const int mg = blockIdx.x;
    const int m0 = mg * 128;
    const int ny = blockIdx.y;

    const __half* __restrict__ hhr = g_hh[t & 1];
    __half* __restrict__ hhw = g_hh[(t + 1) & 1];

    const int grp = lane >> 3, lr = lane & 7;

    // init acc from precomputed x-part preacts (bias included), fp16 -> fp32
    float acc[4][2][2][4];
    {
        size_t blk = (((size_t)t * 32 + mg) * 4 + ny) * 32768;
        #pragma unroll
        for (int fq = 0; fq < 16; ++fq) {
            uint2 v = *(const uint2*)&g_pre[blk + (size_t)fq * 2048 + tid * 4];
            float2 f01 = __half22float2(*(__half2*)&v.x);
            float2 f23 = __half22float2(*(__half2*)&v.y);
            int g = fq >> 2, i = (fq >> 1) & 1, s2 = fq & 1;
            acc[g][i][s2][0] = f01.x; acc[g][i][s2][1] = f01.y;
            acc[g][i][s2][2] = f23.x; acc[g][i][s2][3] = f23.y;
        }
    }

    if (t > 0) {
        auto issue_chunk = [&](int c) {
            uint32_t bb = sbase + (uint32_t)((c % NSTAGE) * STAGE_SZ);
            {
                int row = tid >> 2, seg = tid & 3;
                size_t s = (size_t)(m0 + row) * HDIM + c * 32 + seg * 8;
                CP16(bb + A_OFF + (uint32_t)(row * 80 + seg * 16), &hhr[s]);
            }
            #pragma unroll
            for (int e = 0; e < 2; ++e) {
                int idx = tid + e * 512;
                int row = idx >> 2, seg = idx & 3;
                int gr = ((row >> 6) << 8) + ny * 64 + (row & 63);
                size_t s = (size_t)gr * FH + FDIM + c * 32 + seg * 8;
                CP16(bb + B_OFF + (uint32_t)(row * 80 + seg * 16), &g_Wh[s]);
            }
            CP_COMMIT();
        };

        issue_chunk(0);
        issue_chunk(1);

        for (int c = 0; c < 8; ++c) {
            if (c < 7) { CP_WAITG(1); } else { CP_WAITG(0); }
            __syncthreads();
            if (c + 2 < 8) issue_chunk(c + 2);

            const uint32_t bufb = sbase + (uint32_t)((c % NSTAGE) * STAGE_SZ);
            #pragma unroll
            for (int kh = 0; kh < 2; ++kh) {
                uint32_t ah[2][4];
                const int acol = kh * 32 + (grp >> 1) * 16;
                #pragma unroll
                for (int i = 0; i < 2; ++i) {
                    int arow = wm * 32 + i * 16 + (grp & 1) * 8 + lr;
                    LD4(ah[i], bufb + A_OFF + (uint32_t)(arow * 80 + acol));
                }
                const int bcol = kh * 32 + (grp & 1) * 16;
                #pragma unroll
                for (int g = 0; g < 4; ++g) {
                    uint32_t bh[4];
                    int brow = g * 64 + wn * 16 + ((grp >> 1) << 3) + lr;
                    LD4(bh, bufb + B_OFF + (uint32_t)(brow * 80 + bcol));
                    #pragma unroll
                    for (int i = 0; i < 2; ++i)
                        #pragma unroll
                        for (int s2 = 0; s2 < 2; ++s2) {
                            MMA16816(acc[g][i][s2], ah[i], bh[s2 * 2], bh[s2 * 2 + 1]);
                        }
                }
            }
        }
    }

    // ---- epilogue (biases already folded in) ----
    #pragma unroll
    for (int i = 0; i < 2; ++i)
        #pragma unroll
        for (int s2 = 0; s2 < 2; ++s2) {
            const int col = ny * 64 + wn * 16 + s2 * 8 + (lane & 3) * 2;
            #pragma unroll
            for (int rh = 0; rh < 2; ++rh) {
                int row = m0 + wm * 32 + i * 16 + (lane >> 2) + rh * 8;
                size_t gi = (size_t)row * HDIM + col;
                float2 c2 = (t == 0) ? make_float2(0.0f, 0.0f) : *(float2*)&g_c[gi];
                float cn0 = sigmoidf_(acc[0][i][s2][rh * 2 + 0]) * c2.x
                          + sigmoidf_(acc[1][i][s2][rh * 2 + 0]) * tanhf(acc[2][i][s2][rh * 2 + 0]);
                float cn1 = sigmoidf_(acc[0][i][s2][rh * 2 + 1]) * c2.y
                          + sigmoidf_(acc[1][i][s2][rh * 2 + 1]) * tanhf(acc[2][i][s2][rh * 2 + 1]);
                float hn0 = sigmoidf_(acc[3][i][s2][rh * 2 + 0]) * tanhf(cn0);
                float hn1 = sigmoidf_(acc[3][i][s2][rh * 2 + 1]) * tanhf(cn1);
                *(float2*)&g_c[gi] = make_float2(cn0, cn1);
                *(__half2*)&hhw[gi] = __halves2half2(__float2half(hn0), __float2half(hn1));
            }
        }
}

// ---------------- head ----------------
__global__ void head_kernel(float* __restrict__ out) {
    int w = threadIdx.x >> 5;
    int lane = threadIdx.x & 31;
    int r = blockIdx.x * 8 + w;
    if (r >= BATCH) return;
    const __half* __restrict__ hh = g_hh[TSTEPS & 1] + (size_t)r * HDIM;
    float s = 0.0f;
    #pragma unroll
    for (int k = lane; k < HDIM; k += 32)
        s += __half2float(hh[k]) * g_weff[k];
    #pragma unroll
    for (int off = 16; off > 0; off >>= 1) s += __shfl_down_sync(0xffffffffu, s, off);
    if (lane == 0) out[r] = s + g_beff;
}

// ---------------- launch ----------------
extern "C" void kernel_launch(void* const* d_in, const int* in_sizes, int n_in,
                              void* d_out, int out_size) {
    const float* x   = (const float*)d_in[0];
    const float* Wf  = (const float*)d_in[1];
    const float* bf  = (const float*)d_in[2];
    const float* Wu  = (const float*)d_in[3];
    const float* bu  = (const float*)d_in[4];
    const float* Wc  = (const float*)d_in[5];
    const float* bc  = (const float*)d_in[6];
    const float* Wo  = (const float*)d_in[7];
    const float* bo  = (const float*)d_in[8];
    const float* Wd1 = (const float*)d_in[9];
    const float* bd1 = (const float*)d_in[10];
    const float* Wd2 = (const float*)d_in[11];
    const float* bd2 = (const float*)d_in[12];
    float* out = (float*)d_out;

    static bool attr_set = false;
    if (!attr_set) {
        cudaFuncSetAttribute(lstm_step_mma, cudaFuncAttributeMaxDynamicSharedMemorySize, SMEM_TOTAL);
        cudaFuncSetAttribute(xpre_kernel, cudaFuncAttributeMaxDynamicSharedMemorySize, SMEM_TOTAL);
        attr_set = true;
    }

    split_x_kernel<<<(BATCH * TSTEPS * FDIM + 255) / 256, 256>>>(x);
    build_WT_kernel<<<1024, 128>>>(Wf, Wu, Wc, Wo);
    weff_kernel<<<8, 1024>>>(Wd1, bd1, Wd2, bd2);

    xpre_kernel<<<dim3(TSTEPS * 32, 4), 512, SMEM_TOTAL>>>(bf, bu, bc, bo);

    dim3 grid(32, 4);
    for (int t = 0; t < TSTEPS; ++t) {
        lstm_step_mma<<<grid, 512, SMEM_TOTAL>>>(t);
    }

    head_kernel<<<BATCH / 8, 256>>>(out);
}

// round 14
// speedup vs baseline: 1.3979x; 1.3979x over previous
#include <cuda_runtime.h>
#include <cuda_fp16.h>
#include <math.h>
#include <cstdint>

#define BATCH 4096
#define TSTEPS 60
#define FDIM 128
#define HDIM 256
#define FH 384

// ---------------- device scratch (allocation-free rule) ----------------
__device__ __half g_xh[(size_t)BATCH * TSTEPS * FDIM];
__device__ __half g_hh[2][(size_t)BATCH * HDIM];
__device__ float  g_c[(size_t)BATCH * HDIM];
__device__ __half g_Wh[(size_t)1024 * FH];   // [gate*256+col][k] fp16 weights
__device__ float  g_weff[HDIM];
__device__ float  g_beff;

__device__ __forceinline__ float sigmoidf_(float x) { return 1.0f / (1.0f + __expf(-x)); }

__device__ __forceinline__ uint32_t smem_u32(const void* p) {
    uint32_t a;
    asm("{ .reg .u64 t; cvta.to.shared.u64 t, %1; cvt.u32.u64 %0, t; }" : "=r"(a) : "l"(p));
    return a;
}

#define LD4(R, ADDR) \
    asm volatile("ldmatrix.sync.aligned.m8n8.x4.shared.b16 {%0,%1,%2,%3}, [%4];" \
        : "=r"((R)[0]), "=r"((R)[1]), "=r"((R)[2]), "=r"((R)[3]) : "r"(ADDR))

#define MMA16816(C, A, B0, B1) \
    asm volatile("mma.sync.aligned.m16n8k16.row.col.f32.f16.f16.f32 " \
        "{%0,%1,%2,%3}, {%4,%5,%6,%7}, {%8,%9}, {%0,%1,%2,%3};" \
        : "+f"((C)[0]), "+f"((C)[1]), "+f"((C)[2]), "+f"((C)[3]) \
        : "r"((A)[0]), "r"((A)[1]), "r"((A)[2]), "r"((A)[3]), "r"(B0), "r"(B1))

#define CP16(SADDR, GADDR) \
    asm volatile("cp.async.cg.shared.global [%0], [%1], 16;" :: "r"(SADDR), "l"(GADDR))
#define CP_COMMIT() asm volatile("cp.async.commit_group;")
#define CP_WAITG(N) asm volatile("cp.async.wait_group %0;" :: "n"(N))

// ---------------- prep kernels ----------------
__global__ void split_x_kernel(const float* __restrict__ x) {
    size_t i = (size_t)blockIdx.x * blockDim.x + threadIdx.x;
    if (i < (size_t)BATCH * TSTEPS * FDIM) g_xh[i] = __float2half(x[i]);
}

__global__ void build_WT_kernel(const float* __restrict__ Wf, const float* __restrict__ Wu,
                                const float* __restrict__ Wc, const float* __restrict__ Wo) {
    int gr = blockIdx.x;                 // 0..1023
    int g = gr >> 8, col = gr & 255;
    const float* W = (g == 0) ? Wf : (g == 1) ? Wu : (g == 2) ? Wc : Wo;
    for (int k = threadIdx.x; k < FH; k += blockDim.x) {
        g_Wh[(size_t)gr * FH + k] = __float2half(W[(size_t)k * HDIM + col]);
    }
}

__global__ void weff_kernel(const float* __restrict__ Wd1, const float* __restrict__ bd1,
                            const float* __restrict__ Wd2, const float* __restrict__ bd2) {
    int w = (blockIdx.x * blockDim.x + threadIdx.x) >> 5;
    int lane = threadIdx.x & 31;
    if (w < HDIM) {
        float s = 0.0f;
        #pragma unroll
        for (int k = lane; k < HDIM; k += 32) s += Wd1[(size_t)w * HDIM + k] * Wd2[k];
        #pragma unroll
        for (int off = 16; off > 0; off >>= 1) s += __shfl_down_sync(0xffffffffu, s, off);
        if (lane == 0) g_weff[w] = s;
    }
    if (blockIdx.x == 0 && threadIdx.x < 32) {
        float b = 0.0f;
        #pragma unroll
        for (int k = lane; k < HDIM; k += 32) b += bd1[k] * Wd2[k];
        #pragma unroll
        for (int off = 16; off > 0; off >>= 1) b += __shfl_down_sync(0xffffffffu, b, off);
        if (lane == 0) g_beff = b + bd2[0];
    }
}

// ---------------- shared tile constants (single fp16 pass) ----------------
#define A_OFF 0
#define B_OFF 10240
#define STAGE_SZ 30720
#define NSTAGE 3
#define SMEM_TOTAL (NSTAGE * STAGE_SZ)   // 90 KB

// ---------------- step kernel (fused x+h GEMM, single fp16 pass) ----------------
__global__ __launch_bounds__(512, 1)
void lstm_step_mma(const float* __restrict__ bfv, const float* __restrict__ buv,
                   const float* __restrict__ bcv, const float* __restrict__ bov, int t) {
    extern __shared__ __align__(128) char smem[];
    const uint32_t sbase = smem_u32(smem);
    const int tid = threadIdx.x;
    const int warp = tid >> 5;
    const int lane = tid & 31;
    const int wm = warp >> 2;
    const int wn = warp & 3;
    const int mg = blockIdx.x;
    const int m0 = mg * 128;
    const int ny = blockIdx.y;

    const __half* __restrict__ hhr = g_hh[t & 1];
    __half* __restrict__ hhw = g_hh[(t + 1) & 1];

    const int grp = lane >> 3, lr = lane & 7;
    const int nch = (t == 0) ? 4 : 12;   // h0 == 0: only the x-part contributes

    float acc[4][2][2][4];
    #pragma unroll
    for (int g = 0; g < 4; ++g)
        #pragma unroll
        for (int i = 0; i < 2; ++i)
            #pragma unroll
            for (int s = 0; s < 2; ++s)
                #pragma unroll
                for (int q = 0; q < 4; ++q) acc[g][i][s][q] = 0.0f;

    auto issue_chunk = [&](int c) {
        uint32_t bb = sbase + (uint32_t)((c % NSTAGE) * STAGE_SZ);
        {
            int row = tid >> 2, seg = tid & 3;
            const __half* ph;
            size_t s;
            if (c < 4) {
                s = ((size_t)(m0 + row) * TSTEPS + t) * FDIM + c * 32 + seg * 8;
                ph = g_xh;
            } else {
                s = (size_t)(m0 + row) * HDIM + (c - 4) * 32 + seg * 8;
                ph = hhr;
            }
            CP16(bb + A_OFF + (uint32_t)(row * 80 + seg * 16), &ph[s]);
        }
        #pragma unroll
        for (int e = 0; e < 2; ++e) {
            int idx = tid + e * 512;
            int row = idx >> 2, seg = idx & 3;
            int gr = ((row >> 6) << 8) + ny * 64 + (row & 63);
            size_t s = (size_t)gr * FH + c * 32 + seg * 8;
            CP16(bb + B_OFF + (uint32_t)(row * 80 + seg * 16), &g_Wh[s]);
        }
        CP_COMMIT();
    };

    issue_chunk(0);
    issue_chunk(1);

    for (int c = 0; c < nch; ++c) {
        if (c < nch - 1) { CP_WAITG(1); } else { CP_WAITG(0); }
        __syncthreads();
        if (c + 2 < nch) issue_chunk(c + 2);

        const uint32_t bufb = sbase + (uint32_t)((c % NSTAGE) * STAGE_SZ);
        #pragma unroll
        for (int kh = 0; kh < 2; ++kh) {
            uint32_t ah[2][4];
            const int acol = kh * 32 + (grp >> 1) * 16;
            #pragma unroll
            for (int i = 0; i < 2; ++i) {
                int arow = wm * 32 + i * 16 + (grp & 1) * 8 + lr;
                LD4(ah[i], bufb + A_OFF + (uint32_t)(arow * 80 + acol));
            }
            const int bcol = kh * 32 + (grp & 1) * 16;
            #pragma unroll
            for (int g = 0; g < 4; ++g) {
                uint32_t bh[4];
                int brow = g * 64 + wn * 16 + ((grp >> 1) << 3) + lr;
                LD4(bh, bufb + B_OFF + (uint32_t)(brow * 80 + bcol));
                #pragma unroll
                for (int i = 0; i < 2; ++i)
                    #pragma unroll
                    for (int s2 = 0; s2 < 2; ++s2) {
                        MMA16816(acc[g][i][s2], ah[i], bh[s2 * 2], bh[s2 * 2 + 1]);
                    }
            }
        }
    }

    // ---- epilogue: biases + fused LSTM update (register-local) ----
    #pragma unroll
    for (int i = 0; i < 2; ++i)
        #pragma unroll
        for (int s2 = 0; s2 < 2; ++s2) {
            const int col = ny * 64 + wn * 16 + s2 * 8 + (lane & 3) * 2;
            float2 bF = *(const float2*)&bfv[col];
            float2 bU = *(const float2*)&buv[col];
            float2 bC = *(const float2*)&bcv[col];
            float2 bO = *(const float2*)&bov[col];
            #pragma unroll
            for (int rh = 0; rh < 2; ++rh) {
                int row = m0 + wm * 32 + i * 16 + (lane >> 2) + rh * 8;
                size_t gi = (size_t)row * HDIM + col;
                float2 c2 = (t == 0) ? make_float2(0.0f, 0.0f) : *(float2*)&g_c[gi];
                float fa0 = acc[0][i][s2][rh * 2 + 0] + bF.x;
                float fa1 = acc[0][i][s2][rh * 2 + 1] + bF.y;
                float ua0 = acc[1][i][s2][rh * 2 + 0] + bU.x;
                float ua1 = acc[1][i][s2][rh * 2 + 1] + bU.y;
                float ga0 = acc[2][i][s2][rh * 2 + 0] + bC.x;
                float ga1 = acc[2][i][s2][rh * 2 + 1] + bC.y;
                float oa0 = acc[3][i][s2][rh * 2 + 0] + bO.x;
                float oa1 = acc[3][i][s2][rh * 2 + 1] + bO.y;
                float cn0 = sigmoidf_(fa0) * c2.x + sigmoidf_(ua0) * tanhf(ga0);
                float cn1 = sigmoidf_(fa1) * c2.y + sigmoidf_(ua1) * tanhf(ga1);
                float hn0 = sigmoidf_(oa0) * tanhf(cn0);
                float hn1 = sigmoidf_(oa1) * tanhf(cn1);
                *(float2*)&g_c[gi] = make_float2(cn0, cn1);
                *(__half2*)&hhw[gi] = __halves2half2(__float2half(hn0), __float2half(hn1));
            }
        }
}

// ---------------- head ----------------
__global__ void head_kernel(float* __restrict__ out) {
    int w = threadIdx.x >> 5;
    int lane = threadIdx.x & 31;
    int r = blockIdx.x * 8 + w;
    if (r >= BATCH) return;
    const __half* __restrict__ hh = g_hh[TSTEPS & 1] + (size_t)r * HDIM;
    float s = 0.0f;
    #pragma unroll
    for (int k = lane; k < HDIM; k += 32)
        s += __half2float(hh[k]) * g_weff[k];
    #pragma unroll
    for (int off = 16; off > 0; off >>= 1) s += __shfl_down_sync(0xffffffffu, s, off);
    if (lane == 0) out[r] = s + g_beff;
}

// ---------------- launch ----------------
extern "C" void kernel_launch(void* const* d_in, const int* in_sizes, int n_in,
                              void* d_out, int out_size) {
    const float* x   = (const float*)d_in[0];
    const float* Wf  = (const float*)d_in[1];
    const float* bf  = (const float*)d_in[2];
    const float* Wu  = (const float*)d_in[3];
    const float* bu  = (const float*)d_in[4];
    const float* Wc  = (const float*)d_in[5];
    const float* bc  = (const float*)d_in[6];
    const float* Wo  = (const float*)d_in[7];
    const float* bo  = (const float*)d_in[8];
    const float* Wd1 = (const float*)d_in[9];
    const float* bd1 = (const float*)d_in[10];
    const float* Wd2 = (const float*)d_in[11];
    const float* bd2 = (const float*)d_in[12];
    float* out = (float*)d_out;

    static bool attr_set = false;
    if (!attr_set) {
        cudaFuncSetAttribute(lstm_step_mma, cudaFuncAttributeMaxDynamicSharedMemorySize, SMEM_TOTAL);
        attr_set = true;
    }

    split_x_kernel<<<(BATCH * TSTEPS * FDIM + 255) / 256, 256>>>(x);
    build_WT_kernel<<<1024, 128>>>(Wf, Wu, Wc, Wo);
    weff_kernel<<<8, 1024>>>(Wd1, bd1, Wd2, bd2);

    dim3 grid(32, 4);
    for (int t = 0; t < TSTEPS; ++t) {
        lstm_step_mma<<<grid, 512, SMEM_TOTAL>>>(bf, bu, bc, bo, t);
    }

    head_kernel<<<BATCH / 8, 256>>>(out);
}

// round 16
// speedup vs baseline: 1.4503x; 1.0375x over previous
#include <cuda_runtime.h>
#include <cuda_fp16.h>
#include <math.h>
#include <cstdint>

#define BATCH 4096
#define TSTEPS 60
#define FDIM 128
#define HDIM 256
#define FH 384
#define NCTA 128

// ---------------- device scratch (allocation-free rule) ----------------
__device__ __half g_xh[(size_t)BATCH * TSTEPS * FDIM];
__device__ __half g_hh[2][(size_t)BATCH * HDIM];
__device__ float  g_c[(size_t)BATCH * HDIM];
__device__ __half g_Wh[(size_t)1024 * FH];   // [gate*256+col][k] fp16 weights
__device__ float  g_weff[HDIM];
__device__ float  g_beff;
__device__ int    g_cnt;     // monotonic arrival counter (zeroed per replay)
__device__ int    g_epoch;   // completed-step epoch (zeroed per replay)

__device__ __forceinline__ float sigmoidf_(float x) { return 1.0f / (1.0f + __expf(-x)); }

__device__ __forceinline__ uint32_t smem_u32(const void* p) {
    uint32_t a;
    asm("{ .reg .u64 t; cvta.to.shared.u64 t, %1; cvt.u32.u64 %0, t; }" : "=r"(a) : "l"(p));
    return a;
}

#define LD4(R, ADDR) \
    asm volatile("ldmatrix.sync.aligned.m8n8.x4.shared.b16 {%0,%1,%2,%3}, [%4];" \
        : "=r"((R)[0]), "=r"((R)[1]), "=r"((R)[2]), "=r"((R)[3]) : "r"(ADDR))

#define MMA16816(C, A, B0, B1) \
    asm volatile("mma.sync.aligned.m16n8k16.row.col.f32.f16.f16.f32 " \
        "{%0,%1,%2,%3}, {%4,%5,%6,%7}, {%8,%9}, {%0,%1,%2,%3};" \
        : "+f"((C)[0]), "+f"((C)[1]), "+f"((C)[2]), "+f"((C)[3]) \
        : "r"((A)[0]), "r"((A)[1]), "r"((A)[2]), "r"((A)[3]), "r"(B0), "r"(B1))

#define CP16(SADDR, GADDR) \
    asm volatile("cp.async.cg.shared.global [%0], [%1], 16;" :: "r"(SADDR), "l"(GADDR))
#define CP_COMMIT() asm volatile("cp.async.commit_group;")
#define CP_WAITG(N) asm volatile("cp.async.wait_group %0;" :: "n"(N))

// ---------------- prep kernels ----------------
__global__ void zero_sync_kernel() {
    g_cnt = 0;
    g_epoch = 0;
}

__global__ void split_x_kernel(const float* __restrict__ x) {
    size_t i = (size_t)blockIdx.x * blockDim.x + threadIdx.x;
    if (i < (size_t)BATCH * TSTEPS * FDIM) g_xh[i] = __float2half(x[i]);
}

__global__ void build_WT_kernel(const float* __restrict__ Wf, const float* __restrict__ Wu,
                                const float* __restrict__ Wc, const float* __restrict__ Wo) {
    int gr = blockIdx.x;                 // 0..1023
    int g = gr >> 8, col = gr & 255;
    const float* W = (g == 0) ? Wf : (g == 1) ? Wu : (g == 2) ? Wc : Wo;
    for (int k = threadIdx.x; k < FH; k += blockDim.x) {
        g_Wh[(size_t)gr * FH + k] = __float2half(W[(size_t)k * HDIM + col]);
    }
}

__global__ void weff_kernel(const float* __restrict__ Wd1, const float* __restrict__ bd1,
                            const float* __restrict__ Wd2, const float* __restrict__ bd2) {
    int w = (blockIdx.x * blockDim.x + threadIdx.x) >> 5;
    int lane = threadIdx.x & 31;
    if (w < HDIM) {
        float s = 0.0f;
        #pragma unroll
        for (int k = lane; k < HDIM; k += 32) s += Wd1[(size_t)w * HDIM + k] * Wd2[k];
        #pragma unroll
        for (int off = 16; off > 0; off >>= 1) s += __shfl_down_sync(0xffffffffu, s, off);
        if (lane == 0) g_weff[w] = s;
    }
    if (blockIdx.x == 0 && threadIdx.x < 32) {
        float b = 0.0f;
        #pragma unroll
        for (int k = lane; k < HDIM; k += 32) b += bd1[k] * Wd2[k];
        #pragma unroll
        for (int off = 16; off > 0; off >>= 1) b += __shfl_down_sync(0xffffffffu, b, off);
        if (lane == 0) g_beff = b + bd2[0];
    }
}

// ---------------- shared tile constants (single fp16 pass) ----------------
#define A_OFF 0
#define B_OFF 10240
#define STAGE_SZ 30720
#define NSTAGE 3
#define SMEM_TOTAL (NSTAGE * STAGE_SZ)   // 90 KB

// ---------------- persistent LSTM kernel (all 60 steps, one grid barrier/step) ----------------
__global__ __launch_bounds__(512, 1)
void lstm_persist(const float* __restrict__ bfv, const float* __restrict__ buv,
                  const float* __restrict__ bcv, const float* __restrict__ bov) {
    extern __shared__ __align__(128) char smem[];
    const uint32_t sbase = smem_u32(smem);
    const int tid = threadIdx.x;
    const int warp = tid >> 5;
    const int lane = tid & 31;
    const int wm = warp >> 2;
    const int wn = warp & 3;
    const int mg = blockIdx.x;
    const int m0 = mg * 128;
    const int ny = blockIdx.y;

    const int grp = lane >> 3, lr = lane & 7;

    // per-thread bias fragments (col pattern fixed for the whole kernel)
    float bias_r[4][2][2];   // [gate][s2][x/y]
    {
        #pragma unroll
        for (int s2 = 0; s2 < 2; ++s2) {
            const int col = ny * 64 + wn * 16 + s2 * 8 + (lane & 3) * 2;
            float2 v;
            v = *(const float2*)&bfv[col]; bias_r[0][s2][0] = v.x; bias_r[0][s2][1] = v.y;
            v = *(const float2*)&buv[col]; bias_r[1][s2][0] = v.x; bias_r[1][s2][1] = v.y;
            v = *(const float2*)&bcv[col]; bias_r[2][s2][0] = v.x; bias_r[2][s2][1] = v.y;
            v = *(const float2*)&bov[col]; bias_r[3][s2][0] = v.x; bias_r[3][s2][1] = v.y;
        }
    }

    // issue chunk (tt, cc) into smem stage st
    auto issue_chunk = [&](int tt, int cc, int st) {
        uint32_t bb = sbase + (uint32_t)(st * STAGE_SZ);
        {
            int row = tid >> 2, seg = tid & 3;
            const __half* ph;
            size_t s;
            if (cc < 4) {
                s = ((size_t)(m0 + row) * TSTEPS + tt) * FDIM + cc * 32 + seg * 8;
                ph = g_xh;
            } else {
                s = (size_t)(m0 + row) * HDIM + (cc - 4) * 32 + seg * 8;
                ph = g_hh[tt & 1];
            }
            CP16(bb + A_OFF + (uint32_t)(row * 80 + seg * 16), &ph[s]);
        }
        #pragma unroll
        for (int e = 0; e < 2; ++e) {
            int idx = tid + e * 512;
            int row = idx >> 2, seg = idx & 3;
            int gr = ((row >> 6) << 8) + ny * 64 + (row & 63);
            size_t s = (size_t)gr * FH + cc * 32 + seg * 8;
            CP16(bb + B_OFF + (uint32_t)(row * 80 + seg * 16), &g_Wh[s]);
        }
        CP_COMMIT();
    };

    int ist = 0, cst = 0;   // issue / consume stage counters (mod NSTAGE)

    issue_chunk(0, 0, ist % NSTAGE); ++ist;
    issue_chunk(0, 1, ist % NSTAGE); ++ist;

    for (int t = 0; t < TSTEPS; ++t) {
        const int nch = (t == 0) ? 4 : 12;   // h0 == 0: only the x-part at t=0
        float* __restrict__ cmem = g_c;
        __half* __restrict__ hhw = g_hh[(t + 1) & 1];

        float acc[4][2][2][4];
        #pragma unroll
        for (int g = 0; g < 4; ++g)
            #pragma unroll
            for (int i = 0; i < 2; ++i)
                #pragma unroll
                for (int s = 0; s < 2; ++s) {
                    acc[g][i][s][0] = bias_r[g][s][0];
                    acc[g][i][s][1] = bias_r[g][s][1];
                    acc[g][i][s][2] = bias_r[g][s][0];
                    acc[g][i][s][3] = bias_r[g][s][1];
                }

        for (int c = 0; c < nch; ++c) {
            if (t == TSTEPS - 1 && c == nch - 1) { CP_WAITG(0); } else { CP_WAITG(1); }
            __syncthreads();

            // rolling prefetch: 2 chunks ahead, crossing the step boundary
            int it = t, ic = c + 2;
            if (ic >= nch) { it = t + 1; ic -= nch; }
            if (it < TSTEPS) {
                issue_chunk(it, ic, ist % NSTAGE);   // cross-step chunks are x/W only (ic<2)
            } else {
                CP_COMMIT();                          // uniform group accounting
            }
            ++ist;

            const uint32_t bufb = sbase + (uint32_t)((cst % NSTAGE) * STAGE_SZ);
            ++cst;
            #pragma unroll
            for (int kh = 0; kh < 2; ++kh) {
                uint32_t ah[2][4];
                const int acol = kh * 32 + (grp >> 1) * 16;
                #pragma unroll
                for (int i = 0; i < 2; ++i) {
                    int arow = wm * 32 + i * 16 + (grp & 1) * 8 + lr;
                    LD4(ah[i], bufb + A_OFF + (uint32_t)(arow * 80 + acol));
                }
                const int bcol = kh * 32 + (grp & 1) * 16;
                #pragma unroll
                for (int g = 0; g < 4; ++g) {
                    uint32_t bh[4];
                    int brow = g * 64 + wn * 16 + ((grp >> 1) << 3) + lr;
                    LD4(bh, bufb + B_OFF + (uint32_t)(brow * 80 + bcol));
                    #pragma unroll
                    for (int i = 0; i < 2; ++i)
                        #pragma unroll
                        for (int s2 = 0; s2 < 2; ++s2) {
                            MMA16816(acc[g][i][s2], ah[i], bh[s2 * 2], bh[s2 * 2 + 1]);
                        }
                }
            }
        }

        // ---- epilogue: fused LSTM update (biases pre-folded into acc) ----
        #pragma unroll
        for (int i = 0; i < 2; ++i)
            #pragma unroll
            for (int s2 = 0; s2 < 2; ++s2) {
                const int col = ny * 64 + wn * 16 + s2 * 8 + (lane & 3) * 2;
                #pragma unroll
                for (int rh = 0; rh < 2; ++rh) {
                    int row = m0 + wm * 32 + i * 16 + (lane >> 2) + rh * 8;
                    size_t gi = (size_t)row * HDIM + col;
                    float2 c2 = (t == 0) ? make_float2(0.0f, 0.0f) : *(float2*)&cmem[gi];
                    float cn0 = sigmoidf_(acc[0][i][s2][rh * 2 + 0]) * c2.x
                              + sigmoidf_(acc[1][i][s2][rh * 2 + 0]) * tanhf(acc[2][i][s2][rh * 2 + 0]);
                    float cn1 = sigmoidf_(acc[0][i][s2][rh * 2 + 1]) * c2.y
                              + sigmoidf_(acc[1][i][s2][rh * 2 + 1]) * tanhf(acc[2][i][s2][rh * 2 + 1]);
                    float hn0 = sigmoidf_(acc[3][i][s2][rh * 2 + 0]) * tanhf(cn0);
                    float hn1 = sigmoidf_(acc[3][i][s2][rh * 2 + 1]) * tanhf(cn1);
                    *(float2*)&cmem[gi] = make_float2(cn0, cn1);
                    *(__half2*)&hhw[gi] = __halves2half2(__float2half(hn0), __float2half(hn1));
                }
            }

        // ---- one grid barrier per step (skip after the last step) ----
        if (t < TSTEPS - 1) {
            __threadfence();     // release h/c writes to GPU scope
            __syncthreads();     // all warps of this CTA done
            if (tid == 0) {
                int old = atomicAdd(&g_cnt, 1);
                if (old == NCTA * (t + 1) - 1) {
                    __threadfence();
                    atomicExch(&g_epoch, t + 1);      // release the grid
                } else {
                    while (*(volatile int*)&g_epoch < t + 1) {}
                }
            }
            __syncthreads();     // CTA proceeds only after epoch advanced
        }
    }
}

// ---------------- head ----------------
__global__ void head_kernel(float* __restrict__ out) {
    int w = threadIdx.x >> 5;
    int lane = threadIdx.x & 31;
    int r = blockIdx.x * 8 + w;
    if (r >= BATCH) return;
    const __half* __restrict__ hh = g_hh[TSTEPS & 1] + (size_t)r * HDIM;
    float s = 0.0f;
    #pragma unroll
    for (int k = lane; k < HDIM; k += 32)
        s += __half2float(hh[k]) * g_weff[k];
    #pragma unroll
    for (int off = 16; off > 0; off >>= 1) s += __shfl_down_sync(0xffffffffu, s, off);
    if (lane == 0) out[r] = s + g_beff;
}

// ---------------- launch ----------------
extern "C" void kernel_launch(void* const* d_in, const int* in_sizes, int n_in,
                              void* d_out, int out_size) {
    const float* x   = (const float*)d_in[0];
    const float* Wf  = (const float*)d_in[1];
    const float* bf  = (const float*)d_in[2];
    const float* Wu  = (const float*)d_in[3];
    const float* bu  = (const float*)d_in[4];
    const float* Wc  = (const float*)d_in[5];
    const float* bc  = (const float*)d_in[6];
    const float* Wo  = (const float*)d_in[7];
    const float* bo  = (const float*)d_in[8];
    const float* Wd1 = (const float*)d_in[9];
    const float* bd1 = (const float*)d_in[10];
    const float* Wd2 = (const float*)d_in[11];
    const float* bd2 = (const float*)d_in[12];
    float* out = (float*)d_out;

    static bool attr_set = false;
    if (!attr_set) {
        cudaFuncSetAttribute(lstm_persist, cudaFuncAttributeMaxDynamicSharedMemorySize, SMEM_TOTAL);
        attr_set = true;
    }

    zero_sync_kernel<<<1, 1>>>();
    split_x_kernel<<<(BATCH * TSTEPS * FDIM + 255) / 256, 256>>>(x);
    build_WT_kernel<<<1024, 128>>>(Wf, Wu, Wc, Wo);
    weff_kernel<<<8, 1024>>>(Wd1, bd1, Wd2, bd2);

    dim3 grid(32, 4);
    lstm_persist<<<grid, 512, SMEM_TOTAL>>>(bf, bu, bc, bo);

    head_kernel<<<BATCH / 8, 256>>>(out);
}

// round 17
// speedup vs baseline: 1.4529x; 1.0018x over previous
#include <cuda_runtime.h>
#include <cuda_fp16.h>
#include <math.h>
#include <cstdint>

#define BATCH 4096
#define TSTEPS 60
#define FDIM 128
#define HDIM 256
#define FH 384

// ---------------- device scratch (allocation-free rule) ----------------
__device__ __half g_xh[(size_t)BATCH * TSTEPS * FDIM];
__device__ __half g_hh[2][(size_t)BATCH * HDIM];
__device__ float  g_c[(size_t)BATCH * HDIM];
__device__ __half g_Wh[(size_t)1024 * FH];   // [gate*256+col][k] fp16 weights
__device__ float  g_weff[HDIM];
__device__ float  g_beff;
__device__ int    g_cnt[32 * 32];   // per-mg arrival counters (128B apart)
__device__ int    g_ep[32 * 32];    // per-mg completed-step epochs

__device__ __forceinline__ float sigmoidf_(float x) { return 1.0f / (1.0f + __expf(-x)); }

__device__ __forceinline__ uint32_t smem_u32(const void* p) {
    uint32_t a;
    asm("{ .reg .u64 t; cvta.to.shared.u64 t, %1; cvt.u32.u64 %0, t; }" : "=r"(a) : "l"(p));
    return a;
}

#define LD4(R, ADDR) \
    asm volatile("ldmatrix.sync.aligned.m8n8.x4.shared.b16 {%0,%1,%2,%3}, [%4];" \
        : "=r"((R)[0]), "=r"((R)[1]), "=r"((R)[2]), "=r"((R)[3]) : "r"(ADDR))

#define MMA16816(C, A, B0, B1) \
    asm volatile("mma.sync.aligned.m16n8k16.row.col.f32.f16.f16.f32 " \
        "{%0,%1,%2,%3}, {%4,%5,%6,%7}, {%8,%9}, {%0,%1,%2,%3};" \
        : "+f"((C)[0]), "+f"((C)[1]), "+f"((C)[2]), "+f"((C)[3]) \
        : "r"((A)[0]), "r"((A)[1]), "r"((A)[2]), "r"((A)[3]), "r"(B0), "r"(B1))

#define CP16(SADDR, GADDR) \
    asm volatile("cp.async.cg.shared.global [%0], [%1], 16;" :: "r"(SADDR), "l"(GADDR))
#define CP_COMMIT() asm volatile("cp.async.commit_group;")
#define CP_WAITG(N) asm volatile("cp.async.wait_group %0;" :: "n"(N))

// ---------------- prep kernels ----------------
__global__ void zero_sync_kernel() {
    int i = threadIdx.x;
    if (i < 32 * 32) { g_cnt[i] = 0; g_ep[i] = 0; }
}

__global__ void split_x_kernel(const float* __restrict__ x) {
    size_t i = (size_t)blockIdx.x * blockDim.x + threadIdx.x;
    if (i < (size_t)BATCH * TSTEPS * FDIM) g_xh[i] = __float2half(x[i]);
}

__global__ void build_WT_kernel(const float* __restrict__ Wf, const float* __restrict__ Wu,
                                const float* __restrict__ Wc, const float* __restrict__ Wo) {
    int gr = blockIdx.x;                 // 0..1023
    int g = gr >> 8, col = gr & 255;
    const float* W = (g == 0) ? Wf : (g == 1) ? Wu : (g == 2) ? Wc : Wo;
    for (int k = threadIdx.x; k < FH; k += blockDim.x) {
        g_Wh[(size_t)gr * FH + k] = __float2half(W[(size_t)k * HDIM + col]);
    }
}

__global__ void weff_kernel(const float* __restrict__ Wd1, const float* __restrict__ bd1,
                            const float* __restrict__ Wd2, const float* __restrict__ bd2) {
    int w = (blockIdx.x * blockDim.x + threadIdx.x) >> 5;
    int lane = threadIdx.x & 31;
    if (w < HDIM) {
        float s = 0.0f;
        #pragma unroll
        for (int k = lane; k < HDIM; k += 32) s += Wd1[(size_t)w * HDIM + k] * Wd2[k];
        #pragma unroll
        for (int off = 16; off > 0; off >>= 1) s += __shfl_down_sync(0xffffffffu, s, off);
        if (lane == 0) g_weff[w] = s;
    }
    if (blockIdx.x == 0 && threadIdx.x < 32) {
        float b = 0.0f;
        #pragma unroll
        for (int k = lane; k < HDIM; k += 32) b += bd1[k] * Wd2[k];
        #pragma unroll
        for (int off = 16; off > 0; off >>= 1) b += __shfl_down_sync(0xffffffffu, b, off);
        if (lane == 0) g_beff = b + bd2[0];
    }
}

// ---------------- shared tile constants (single fp16 pass) ----------------
#define A_OFF 0
#define B_OFF 10240
#define STAGE_SZ 30720
#define NSTAGE 3
#define SMEM_TOTAL (NSTAGE * STAGE_SZ)   // 90 KB

// ---------------- persistent LSTM kernel (per-mg 4-CTA barriers, deferred wait) ----------------
__global__ __launch_bounds__(512, 1)
void lstm_persist(const float* __restrict__ bfv, const float* __restrict__ buv,
                  const float* __restrict__ bcv, const float* __restrict__ bov) {
    extern __shared__ __align__(128) char smem[];
    const uint32_t sbase = smem_u32(smem);
    const int tid = threadIdx.x;
    const int warp = tid >> 5;
    const int lane = tid & 31;
    const int wm = warp >> 2;
    const int wn = warp & 3;
    const int mg = blockIdx.x;
    const int m0 = mg * 128;
    const int ny = blockIdx.y;

    const int grp = lane >> 3, lr = lane & 7;
    int* const my_cnt = &g_cnt[mg * 32];
    volatile int* const my_ep = (volatile int*)&g_ep[mg * 32];

    // per-thread bias fragments (col pattern fixed for the whole kernel)
    float bias_r[4][2][2];   // [gate][s2][x/y]
    {
        #pragma unroll
        for (int s2 = 0; s2 < 2; ++s2) {
            const int col = ny * 64 + wn * 16 + s2 * 8 + (lane & 3) * 2;
            float2 v;
            v = *(const float2*)&bfv[col]; bias_r[0][s2][0] = v.x; bias_r[0][s2][1] = v.y;
            v = *(const float2*)&buv[col]; bias_r[1][s2][0] = v.x; bias_r[1][s2][1] = v.y;
            v = *(const float2*)&bcv[col]; bias_r[2][s2][0] = v.x; bias_r[2][s2][1] = v.y;
            v = *(const float2*)&bov[col]; bias_r[3][s2][0] = v.x; bias_r[3][s2][1] = v.y;
        }
    }

    // issue chunk (tt, cc) into smem stage st
    auto issue_chunk = [&](int tt, int cc, int st) {
        uint32_t bb = sbase + (uint32_t)(st * STAGE_SZ);
        {
            int row = tid >> 2, seg = tid & 3;
            const __half* ph;
            size_t s;
            if (cc < 4) {
                s = ((size_t)(m0 + row) * TSTEPS + tt) * FDIM + cc * 32 + seg * 8;
                ph = g_xh;
            } else {
                s = (size_t)(m0 + row) * HDIM + (cc - 4) * 32 + seg * 8;
                ph = g_hh[tt & 1];
            }
            CP16(bb + A_OFF + (uint32_t)(row * 80 + seg * 16), &ph[s]);
        }
        #pragma unroll
        for (int e = 0; e < 2; ++e) {
            int idx = tid + e * 512;
            int row = idx >> 2, seg = idx & 3;
            int gr = ((row >> 6) << 8) + ny * 64 + (row & 63);
            size_t s = (size_t)gr * FH + cc * 32 + seg * 8;
            CP16(bb + B_OFF + (uint32_t)(row * 80 + seg * 16), &g_Wh[s]);
        }
        CP_COMMIT();
    };

    int ist = 0, cst = 0;   // issue / consume stage counters (mod NSTAGE)

    issue_chunk(0, 0, ist % NSTAGE); ++ist;
    issue_chunk(0, 1, ist % NSTAGE); ++ist;

    for (int t = 0; t < TSTEPS; ++t) {
        const int nch = (t == 0) ? 4 : 12;   // h0 == 0: only the x-part at t=0
        float* __restrict__ cmem = g_c;
        __half* __restrict__ hhw = g_hh[(t + 1) & 1];

        float acc[4][2][2][4];
        #pragma unroll
        for (int g = 0; g < 4; ++g)
            #pragma unroll
            for (int i = 0; i < 2; ++i)
                #pragma unroll
                for (int s = 0; s < 2; ++s) {
                    acc[g][i][s][0] = bias_r[g][s][0];
                    acc[g][i][s][1] = bias_r[g][s][1];
                    acc[g][i][s][2] = bias_r[g][s][0];
                    acc[g][i][s][3] = bias_r[g][s][1];
                }

        for (int c = 0; c < nch; ++c) {
            if (t == TSTEPS - 1 && c == nch - 1) { CP_WAITG(0); } else { CP_WAITG(1); }
            __syncthreads();

            // deferred sibling wait: before the first h-chunk issue of this step
            if (c == 2 && t > 0) {
                if (tid == 0) { while (*my_ep < t) {} }
                __syncthreads();
            }

            // rolling prefetch: 2 chunks ahead, crossing the step boundary (x-only there)
            int it = t, ic = c + 2;
            if (ic >= nch) { it = t + 1; ic -= nch; }
            if (it < TSTEPS) {
                issue_chunk(it, ic, ist % NSTAGE);
            } else {
                CP_COMMIT();                          // uniform group accounting
            }
            ++ist;

            const uint32_t bufb = sbase + (uint32_t)((cst % NSTAGE) * STAGE_SZ);
            ++cst;
            #pragma unroll
            for (int kh = 0; kh < 2; ++kh) {
                uint32_t ah[2][4];
                const int acol = kh * 32 + (grp >> 1) * 16;
                #pragma unroll
                for (int i = 0; i < 2; ++i) {
                    int arow = wm * 32 + i * 16 + (grp & 1) * 8 + lr;
                    LD4(ah[i], bufb + A_OFF + (uint32_t)(arow * 80 + acol));
                }
                const int bcol = kh * 32 + (grp & 1) * 16;
                #pragma unroll
                for (int g = 0; g < 4; ++g) {
                    uint32_t bh[4];
                    int brow = g * 64 + wn * 16 + ((grp >> 1) << 3) + lr;
                    LD4(bh, bufb + B_OFF + (uint32_t)(brow * 80 + bcol));
                    #pragma unroll
                    for (int i = 0; i < 2; ++i)
                        #pragma unroll
                        for (int s2 = 0; s2 < 2; ++s2) {
                            MMA16816(acc[g][i][s2], ah[i], bh[s2 * 2], bh[s2 * 2 + 1]);
                        }
                }
            }
        }

        // ---- epilogue: fused LSTM update (biases pre-folded into acc) ----
        #pragma unroll
        for (int i = 0; i < 2; ++i)
            #pragma unroll
            for (int s2 = 0; s2 < 2; ++s2) {
                const int col = ny * 64 + wn * 16 + s2 * 8 + (lane & 3) * 2;
                #pragma unroll
                for (int rh = 0; rh < 2; ++rh) {
                    int row = m0 + wm * 32 + i * 16 + (lane >> 2) + rh * 8;
                    size_t gi = (size_t)row * HDIM + col;
                    float2 c2 = (t == 0) ? make_float2(0.0f, 0.0f) : *(float2*)&cmem[gi];
                    float cn0 = sigmoidf_(acc[0][i][s2][rh * 2 + 0]) * c2.x
                              + sigmoidf_(acc[1][i][s2][rh * 2 + 0]) * tanhf(acc[2][i][s2][rh * 2 + 0]);
                    float cn1 = sigmoidf_(acc[0][i][s2][rh * 2 + 1]) * c2.y
                              + sigmoidf_(acc[1][i][s2][rh * 2 + 1]) * tanhf(acc[2][i][s2][rh * 2 + 1]);
                    float hn0 = sigmoidf_(acc[3][i][s2][rh * 2 + 0]) * tanhf(cn0);
                    float hn1 = sigmoidf_(acc[3][i][s2][rh * 2 + 1]) * tanhf(cn1);
                    *(float2*)&cmem[gi] = make_float2(cn0, cn1);
                    *(__half2*)&hhw[gi] = __halves2half2(__float2half(hn0), __float2half(hn1));
                }
            }

        // ---- per-mg arrival (4 CTAs); no wait here — wait is deferred to next step c==2 ----
        if (t < TSTEPS - 1) {
            __threadfence();     // release h/c writes
            __syncthreads();     // all warps of this CTA done writing
            if (tid == 0) {
                int old = atomicAdd(my_cnt, 1);
                if (old == 4 * (t + 1) - 1) {
                    __threadfence();
                    atomicExch((int*)my_ep, t + 1);   // release the mg-group
                }
            }
        }
    }
}

// ---------------- head ----------------
__global__ void head_kernel(float* __restrict__ out) {
    int w = threadIdx.x >> 5;
    int lane = threadIdx.x & 31;
    int r = blockIdx.x * 8 + w;
    if (r >= BATCH) return;
    const __half* __restrict__ hh = g_hh[TSTEPS & 1] + (size_t)r * HDIM;
    float s = 0.0f;
    #pragma unroll
    for (int k = lane; k < HDIM; k += 32)
        s += __half2float(hh[k]) * g_weff[k];
    #pragma unroll
    for (int off = 16; off > 0; off >>= 1) s += __shfl_down_sync(0xffffffffu, s, off);
    if (lane == 0) out[r] = s + g_beff;
}

// ---------------- launch ----------------
extern "C" void kernel_launch(void* const* d_in, const int* in_sizes, int n_in,
                              void* d_out, int out_size) {
    const float* x   = (const float*)d_in[0];
    const float* Wf  = (const float*)d_in[1];
    const float* bf  = (const float*)d_in[2];
    const float* Wu  = (const float*)d_in[3];
    const float* bu  = (const float*)d_in[4];
    const float* Wc  = (const float*)d_in[5];
    const float* bc  = (const float*)d_in[6];
    const float* Wo  = (const float*)d_in[7];
    const float* bo  = (const float*)d_in[8];
    const float* Wd1 = (const float*)d_in[9];
    const float* bd1 = (const float*)d_in[10];
    const float* Wd2 = (const float*)d_in[11];
    const float* bd2 = (const float*)d_in[12];
    float* out = (float*)d_out;

    static bool attr_set = false;
    if (!attr_set) {
        cudaFuncSetAttribute(lstm_persist, cudaFuncAttributeMaxDynamicSharedMemorySize, SMEM_TOTAL);
        attr_set = true;
    }

    zero_sync_kernel<<<1, 1024>>>();
    split_x_kernel<<<(BATCH * TSTEPS * FDIM + 255) / 256, 256>>>(x);
    build_WT_kernel<<<1024, 128>>>(Wf, Wu, Wc, Wo);
    weff_kernel<<<8, 1024>>>(Wd1, bd1, Wd2, bd2);

    dim3 grid(32, 4);
    lstm_persist<<<grid, 512, SMEM_TOTAL>>>(bf, bu, bc, bo);

    head_kernel<<<BATCH / 8, 256>>>(out);
}